// round 12
// baseline (speedup 1.0000x reference)
#include <cuda_runtime.h>
#include <math.h>

#define NTOK 1024          // B*S = 2*512
#define HDIM 2048
#define NEXP 16
#define IDIM 1408

// ---------------- scratch (static device globals; no allocations) ----------
__device__ int   g_cnt[NEXP];
__device__ int   g_tok[NEXP * NTOK];   // packed: token*2 + slot
__device__ float g_wt [NEXP * NTOK];   // renormalized routing weight
__device__ float g_act[2 * NTOK * IDIM]; // silu(g)*u per (token,slot): [2048][1408]

// ---------------- kernel 0: zero counters ----------------------------------
__global__ void zero_counts_kernel() {
    if (threadIdx.x < NEXP) g_cnt[threadIdx.x] = 0;
}

// ---------------- kernel 1: router -----------------------------------------
// One block per token. 8 warps; warp w computes logits for experts w and w+8.
// top-2 of softmax == top-2 of logits; effective weights = sigmoid(l1-l2), 1-..
__global__ void router_kernel(const float* __restrict__ x,
                              const float* __restrict__ gw) {
    const int t = blockIdx.x;
    const float* xr = x + (size_t)t * HDIM;
    __shared__ float logits[NEXP];

    const int warp = threadIdx.x >> 5;
    const int lane = threadIdx.x & 31;

    for (int e = warp; e < NEXP; e += 8) {
        const float* w = gw + (size_t)e * HDIM;
        float s = 0.f;
        for (int k = lane; k < HDIM; k += 32)
            s = fmaf(xr[k], w[k], s);
        #pragma unroll
        for (int o = 16; o; o >>= 1) s += __shfl_xor_sync(0xffffffffu, s, o);
        if (lane == 0) logits[e] = s;
    }
    __syncthreads();

    if (threadIdx.x == 0) {
        int e1 = 0; float l1 = logits[0];
        #pragma unroll
        for (int e = 1; e < NEXP; e++)
            if (logits[e] > l1) { l1 = logits[e]; e1 = e; }
        int e2 = -1; float l2 = -INFINITY;
        #pragma unroll
        for (int e = 0; e < NEXP; e++)
            if (e != e1 && logits[e] > l2) { l2 = logits[e]; e2 = e; }
        // p1/(p1+p2) with pi = softmax probs -> sigmoid of logit diff
        float w1 = 1.f / (1.f + expf(l2 - l1));
        float w2 = 1.f - w1;
        int p1 = atomicAdd(&g_cnt[e1], 1);
        g_tok[e1 * NTOK + p1] = t * 2 + 0;
        g_wt [e1 * NTOK + p1] = w1;
        int p2 = atomicAdd(&g_cnt[e2], 1);
        g_tok[e2 * NTOK + p2] = t * 2 + 1;
        g_wt [e2 * NTOK + p2] = w2;
    }
}

// ---------------- kernel 2: gate/up GEMM + SwiGLU --------------------------
// Per expert: act[tok_slot][i] = silu(x @ Wg) * (x @ Wu), 64x64 tiles, K=16.
// 256 threads, each computes 4x4 for gate and 4x4 for up.
__global__ __launch_bounds__(256)
void gemm1_kernel(const float* __restrict__ x,
                  const float* __restrict__ wg,
                  const float* __restrict__ wu) {
    const int e   = blockIdx.z;
    const int cnt = g_cnt[e];
    const int m0  = blockIdx.y * 64;
    if (m0 >= cnt) return;
    const int n0  = blockIdx.x * 64;

    __shared__ __align__(16) float Xs[16][64];
    __shared__ __align__(16) float Gs[16][64];
    __shared__ __align__(16) float Us[16][64];
    __shared__ int   toks[64];

    const int tid = threadIdx.x;
    if (tid < 64) {
        int r = m0 + tid;
        toks[tid] = (r < cnt) ? g_tok[e * NTOK + r] : -1;
    }
    __syncthreads();

    const int tx = tid & 15;        // I-dim, 4 cols each
    const int ty = tid >> 4;        // token-dim, 4 rows each
    float accG[4][4] = {};
    float accU[4][4] = {};

    const float* wgE = wg + (size_t)e * HDIM * IDIM;
    const float* wuE = wu + (size_t)e * HDIM * IDIM;

    // loader indices
    const int xrow = tid >> 2;              // 0..63
    const int xkq  = (tid & 3) * 4;         // 0,4,8,12
    const int wkk  = tid >> 4;              // 0..15
    const int wiq  = (tid & 15) * 4;        // 0..60

    const int pk_mine = toks[xrow];

    for (int k0 = 0; k0 < HDIM; k0 += 16) {
        // X tile: gathered rows
        float4 v = make_float4(0.f, 0.f, 0.f, 0.f);
        if (pk_mine >= 0)
            v = *(const float4*)&x[(size_t)(pk_mine >> 1) * HDIM + k0 + xkq];
        Xs[xkq + 0][xrow] = v.x;
        Xs[xkq + 1][xrow] = v.y;
        Xs[xkq + 2][xrow] = v.z;
        Xs[xkq + 3][xrow] = v.w;
        // weight tiles (row-major [H][I], contiguous in I -> coalesced)
        *(float4*)&Gs[wkk][wiq] = *(const float4*)&wgE[(size_t)(k0 + wkk) * IDIM + n0 + wiq];
        *(float4*)&Us[wkk][wiq] = *(const float4*)&wuE[(size_t)(k0 + wkk) * IDIM + n0 + wiq];
        __syncthreads();

        #pragma unroll
        for (int kk = 0; kk < 16; kk++) {
            float4 a4 = *(const float4*)&Xs[kk][ty * 4];
            float4 g4 = *(const float4*)&Gs[kk][tx * 4];
            float4 u4 = *(const float4*)&Us[kk][tx * 4];
            float av[4] = {a4.x, a4.y, a4.z, a4.w};
            float gv[4] = {g4.x, g4.y, g4.z, g4.w};
            float uv[4] = {u4.x, u4.y, u4.z, u4.w};
            #pragma unroll
            for (int r = 0; r < 4; r++)
                #pragma unroll
                for (int c = 0; c < 4; c++) {
                    accG[r][c] = fmaf(av[r], gv[c], accG[r][c]);
                    accU[r][c] = fmaf(av[r], uv[c], accU[r][c]);
                }
        }
        __syncthreads();
    }

    // epilogue: silu(g)*u -> g_act
    #pragma unroll
    for (int r = 0; r < 4; r++) {
        int row = ty * 4 + r;
        int pk  = toks[row];
        if (pk < 0) continue;
        float4 o;
        {
            float g = accG[r][0], u = accU[r][0];
            o.x = (g / (1.f + expf(-g))) * u;
            g = accG[r][1]; u = accU[r][1];
            o.y = (g / (1.f + expf(-g))) * u;
            g = accG[r][2]; u = accU[r][2];
            o.z = (g / (1.f + expf(-g))) * u;
            g = accG[r][3]; u = accU[r][3];
            o.w = (g / (1.f + expf(-g))) * u;
        }
        *(float4*)&g_act[(size_t)pk * IDIM + n0 + tx * 4] = o;
    }
}

// ---------------- kernel 3: down GEMM + weighted scatter -------------------
// out[tok][h] += w * (act[tok_slot] @ w_down[e]); 64x64 tiles, K over IDIM.
__global__ __launch_bounds__(256)
void gemm2_kernel(const float* __restrict__ wd,
                  float* __restrict__ out) {
    const int e   = blockIdx.z;
    const int cnt = g_cnt[e];
    const int m0  = blockIdx.y * 64;
    if (m0 >= cnt) return;
    const int n0  = blockIdx.x * 64;

    __shared__ __align__(16) float As[16][64];
    __shared__ __align__(16) float Bs[16][64];
    __shared__ int   toks[64];
    __shared__ float wts[64];

    const int tid = threadIdx.x;
    if (tid < 64) {
        int r = m0 + tid;
        if (r < cnt) {
            toks[tid] = g_tok[e * NTOK + r];
            wts[tid]  = g_wt [e * NTOK + r];
        } else {
            toks[tid] = -1;
            wts[tid]  = 0.f;
        }
    }
    __syncthreads();

    const int tx = tid & 15;
    const int ty = tid >> 4;
    float acc[4][4] = {};

    const float* wdE = wd + (size_t)e * IDIM * HDIM;

    const int arow = tid >> 2;
    const int akq  = (tid & 3) * 4;
    const int wkk  = tid >> 4;
    const int whq  = (tid & 15) * 4;

    const int pk_mine = toks[arow];

    for (int k0 = 0; k0 < IDIM; k0 += 16) {
        float4 v = make_float4(0.f, 0.f, 0.f, 0.f);
        if (pk_mine >= 0)
            v = *(const float4*)&g_act[(size_t)pk_mine * IDIM + k0 + akq];
        As[akq + 0][arow] = v.x;
        As[akq + 1][arow] = v.y;
        As[akq + 2][arow] = v.z;
        As[akq + 3][arow] = v.w;
        *(float4*)&Bs[wkk][whq] = *(const float4*)&wdE[(size_t)(k0 + wkk) * HDIM + n0 + whq];
        __syncthreads();

        #pragma unroll
        for (int kk = 0; kk < 16; kk++) {
            float4 a4 = *(const float4*)&As[kk][ty * 4];
            float4 b4 = *(const float4*)&Bs[kk][tx * 4];
            float av[4] = {a4.x, a4.y, a4.z, a4.w};
            float bv[4] = {b4.x, b4.y, b4.z, b4.w};
            #pragma unroll
            for (int r = 0; r < 4; r++)
                #pragma unroll
                for (int c = 0; c < 4; c++)
                    acc[r][c] = fmaf(av[r], bv[c], acc[r][c]);
        }
        __syncthreads();
    }

    #pragma unroll
    for (int r = 0; r < 4; r++) {
        int row = ty * 4 + r;
        int pk  = toks[row];
        if (pk < 0) continue;
        float w   = wts[row];
        int   tok = pk >> 1;
        float* dst = &out[(size_t)tok * HDIM + n0 + tx * 4];
        #pragma unroll
        for (int c = 0; c < 4; c++)
            atomicAdd(dst + c, w * acc[r][c]);
    }
}

// ---------------- launch ----------------------------------------------------
extern "C" void kernel_launch(void* const* d_in, const int* in_sizes, int n_in,
                              void* d_out, int out_size) {
    const float* x   = (const float*)d_in[0];  // [B,S,H] = [1024, 2048]
    const float* gw  = (const float*)d_in[1];  // [E, H]
    const float* wg  = (const float*)d_in[2];  // [E, H, I]
    const float* wu  = (const float*)d_in[3];  // [E, H, I]
    const float* wd  = (const float*)d_in[4];  // [E, I, H]
    float* out = (float*)d_out;                // [1024, 2048] f32

    cudaMemsetAsync(out, 0, (size_t)NTOK * HDIM * sizeof(float), 0);
    zero_counts_kernel<<<1, 32>>>();
    router_kernel<<<NTOK, 256>>>(x, gw);

    dim3 g1(IDIM / 64, NTOK / 64, NEXP);   // (22, 16, 16), most tiles early-exit
    gemm1_kernel<<<g1, 256>>>(x, wg, wu);

    dim3 g2(HDIM / 64, NTOK / 64, NEXP);   // (32, 16, 16)
    gemm2_kernel<<<g2, 256>>>(wd, out);
}

// round 13
// speedup vs baseline: 1.0007x; 1.0007x over previous
#include <cuda_runtime.h>
#include <math.h>

#define NTOK 1024          // B*S = 2*512
#define HDIM 2048
#define NEXP 16
#define IDIM 1408

// ---------------- scratch (static device globals; no allocations) ----------
__device__ int   g_cnt[NEXP];
__device__ int   g_tok[NEXP * NTOK];   // packed: token*2 + slot
__device__ float g_wt [NEXP * NTOK];   // renormalized routing weight
__device__ float g_act[2 * NTOK * IDIM]; // silu(g)*u per (token,slot): [2048][1408]

// ---------------- kernel 0: zero counters ----------------------------------
__global__ void zero_counts_kernel() {
    if (threadIdx.x < NEXP) g_cnt[threadIdx.x] = 0;
}

// ---------------- kernel 1: router -----------------------------------------
// One block per token. 8 warps; warp w computes logits for experts w and w+8.
// top-2 of softmax == top-2 of logits; effective weights = sigmoid(l1-l2), 1-..
__global__ void router_kernel(const float* __restrict__ x,
                              const float* __restrict__ gw) {
    const int t = blockIdx.x;
    const float* xr = x + (size_t)t * HDIM;
    __shared__ float logits[NEXP];

    const int warp = threadIdx.x >> 5;
    const int lane = threadIdx.x & 31;

    for (int e = warp; e < NEXP; e += 8) {
        const float* w = gw + (size_t)e * HDIM;
        float s = 0.f;
        for (int k = lane; k < HDIM; k += 32)
            s = fmaf(xr[k], w[k], s);
        #pragma unroll
        for (int o = 16; o; o >>= 1) s += __shfl_xor_sync(0xffffffffu, s, o);
        if (lane == 0) logits[e] = s;
    }
    __syncthreads();

    if (threadIdx.x == 0) {
        int e1 = 0; float l1 = logits[0];
        #pragma unroll
        for (int e = 1; e < NEXP; e++)
            if (logits[e] > l1) { l1 = logits[e]; e1 = e; }
        int e2 = -1; float l2 = -INFINITY;
        #pragma unroll
        for (int e = 0; e < NEXP; e++)
            if (e != e1 && logits[e] > l2) { l2 = logits[e]; e2 = e; }
        // p1/(p1+p2) with pi = softmax probs -> sigmoid of logit diff
        float w1 = 1.f / (1.f + expf(l2 - l1));
        float w2 = 1.f - w1;
        int p1 = atomicAdd(&g_cnt[e1], 1);
        g_tok[e1 * NTOK + p1] = t * 2 + 0;
        g_wt [e1 * NTOK + p1] = w1;
        int p2 = atomicAdd(&g_cnt[e2], 1);
        g_tok[e2 * NTOK + p2] = t * 2 + 1;
        g_wt [e2 * NTOK + p2] = w2;
    }
}

// ---------------- kernel 2: gate/up GEMM + SwiGLU --------------------------
// Per expert: act[tok_slot][i] = silu(x @ Wg) * (x @ Wu), 64x64 tiles, K=16.
// 256 threads, each computes 4x4 for gate and 4x4 for up.
__global__ __launch_bounds__(256)
void gemm1_kernel(const float* __restrict__ x,
                  const float* __restrict__ wg,
                  const float* __restrict__ wu) {
    const int e   = blockIdx.z;
    const int cnt = g_cnt[e];
    const int m0  = blockIdx.y * 64;
    if (m0 >= cnt) return;
    const int n0  = blockIdx.x * 64;

    __shared__ __align__(16) float Xs[16][64];
    __shared__ __align__(16) float Gs[16][64];
    __shared__ __align__(16) float Us[16][64];
    __shared__ int   toks[64];

    const int tid = threadIdx.x;
    if (tid < 64) {
        int r = m0 + tid;
        toks[tid] = (r < cnt) ? g_tok[e * NTOK + r] : -1;
    }
    __syncthreads();

    const int tx = tid & 15;        // I-dim, 4 cols each
    const int ty = tid >> 4;        // token-dim, 4 rows each
    float accG[4][4] = {};
    float accU[4][4] = {};

    const float* wgE = wg + (size_t)e * HDIM * IDIM;
    const float* wuE = wu + (size_t)e * HDIM * IDIM;

    // loader indices
    const int xrow = tid >> 2;              // 0..63
    const int xkq  = (tid & 3) * 4;         // 0,4,8,12
    const int wkk  = tid >> 4;              // 0..15
    const int wiq  = (tid & 15) * 4;        // 0..60

    const int pk_mine = toks[xrow];

    for (int k0 = 0; k0 < HDIM; k0 += 16) {
        // X tile: gathered rows
        float4 v = make_float4(0.f, 0.f, 0.f, 0.f);
        if (pk_mine >= 0)
            v = *(const float4*)&x[(size_t)(pk_mine >> 1) * HDIM + k0 + xkq];
        Xs[xkq + 0][xrow] = v.x;
        Xs[xkq + 1][xrow] = v.y;
        Xs[xkq + 2][xrow] = v.z;
        Xs[xkq + 3][xrow] = v.w;
        // weight tiles (row-major [H][I], contiguous in I -> coalesced)
        *(float4*)&Gs[wkk][wiq] = *(const float4*)&wgE[(size_t)(k0 + wkk) * IDIM + n0 + wiq];
        *(float4*)&Us[wkk][wiq] = *(const float4*)&wuE[(size_t)(k0 + wkk) * IDIM + n0 + wiq];
        __syncthreads();

        #pragma unroll
        for (int kk = 0; kk < 16; kk++) {
            float4 a4 = *(const float4*)&Xs[kk][ty * 4];
            float4 g4 = *(const float4*)&Gs[kk][tx * 4];
            float4 u4 = *(const float4*)&Us[kk][tx * 4];
            float av[4] = {a4.x, a4.y, a4.z, a4.w};
            float gv[4] = {g4.x, g4.y, g4.z, g4.w};
            float uv[4] = {u4.x, u4.y, u4.z, u4.w};
            #pragma unroll
            for (int r = 0; r < 4; r++)
                #pragma unroll
                for (int c = 0; c < 4; c++) {
                    accG[r][c] = fmaf(av[r], gv[c], accG[r][c]);
                    accU[r][c] = fmaf(av[r], uv[c], accU[r][c]);
                }
        }
        __syncthreads();
    }

    // epilogue: silu(g)*u -> g_act
    #pragma unroll
    for (int r = 0; r < 4; r++) {
        int row = ty * 4 + r;
        int pk  = toks[row];
        if (pk < 0) continue;
        float4 o;
        {
            float g = accG[r][0], u = accU[r][0];
            o.x = (g / (1.f + expf(-g))) * u;
            g = accG[r][1]; u = accU[r][1];
            o.y = (g / (1.f + expf(-g))) * u;
            g = accG[r][2]; u = accU[r][2];
            o.z = (g / (1.f + expf(-g))) * u;
            g = accG[r][3]; u = accU[r][3];
            o.w = (g / (1.f + expf(-g))) * u;
        }
        *(float4*)&g_act[(size_t)pk * IDIM + n0 + tx * 4] = o;
    }
}

// ---------------- kernel 3: down GEMM + weighted scatter -------------------
// out[tok][h] += w * (act[tok_slot] @ w_down[e]); 64x64 tiles, K over IDIM.
__global__ __launch_bounds__(256)
void gemm2_kernel(const float* __restrict__ wd,
                  float* __restrict__ out) {
    const int e   = blockIdx.z;
    const int cnt = g_cnt[e];
    const int m0  = blockIdx.y * 64;
    if (m0 >= cnt) return;
    const int n0  = blockIdx.x * 64;

    __shared__ __align__(16) float As[16][64];
    __shared__ __align__(16) float Bs[16][64];
    __shared__ int   toks[64];
    __shared__ float wts[64];

    const int tid = threadIdx.x;
    if (tid < 64) {
        int r = m0 + tid;
        if (r < cnt) {
            toks[tid] = g_tok[e * NTOK + r];
            wts[tid]  = g_wt [e * NTOK + r];
        } else {
            toks[tid] = -1;
            wts[tid]  = 0.f;
        }
    }
    __syncthreads();

    const int tx = tid & 15;
    const int ty = tid >> 4;
    float acc[4][4] = {};

    const float* wdE = wd + (size_t)e * IDIM * HDIM;

    const int arow = tid >> 2;
    const int akq  = (tid & 3) * 4;
    const int wkk  = tid >> 4;
    const int whq  = (tid & 15) * 4;

    const int pk_mine = toks[arow];

    for (int k0 = 0; k0 < IDIM; k0 += 16) {
        float4 v = make_float4(0.f, 0.f, 0.f, 0.f);
        if (pk_mine >= 0)
            v = *(const float4*)&g_act[(size_t)pk_mine * IDIM + k0 + akq];
        As[akq + 0][arow] = v.x;
        As[akq + 1][arow] = v.y;
        As[akq + 2][arow] = v.z;
        As[akq + 3][arow] = v.w;
        *(float4*)&Bs[wkk][whq] = *(const float4*)&wdE[(size_t)(k0 + wkk) * HDIM + n0 + whq];
        __syncthreads();

        #pragma unroll
        for (int kk = 0; kk < 16; kk++) {
            float4 a4 = *(const float4*)&As[kk][ty * 4];
            float4 b4 = *(const float4*)&Bs[kk][tx * 4];
            float av[4] = {a4.x, a4.y, a4.z, a4.w};
            float bv[4] = {b4.x, b4.y, b4.z, b4.w};
            #pragma unroll
            for (int r = 0; r < 4; r++)
                #pragma unroll
                for (int c = 0; c < 4; c++)
                    acc[r][c] = fmaf(av[r], bv[c], acc[r][c]);
        }
        __syncthreads();
    }

    #pragma unroll
    for (int r = 0; r < 4; r++) {
        int row = ty * 4 + r;
        int pk  = toks[row];
        if (pk < 0) continue;
        float w   = wts[row];
        int   tok = pk >> 1;
        float* dst = &out[(size_t)tok * HDIM + n0 + tx * 4];
        #pragma unroll
        for (int c = 0; c < 4; c++)
            atomicAdd(dst + c, w * acc[r][c]);
    }
}

// ---------------- launch ----------------------------------------------------
extern "C" void kernel_launch(void* const* d_in, const int* in_sizes, int n_in,
                              void* d_out, int out_size) {
    const float* x   = (const float*)d_in[0];  // [B,S,H] = [1024, 2048]
    const float* gw  = (const float*)d_in[1];  // [E, H]
    const float* wg  = (const float*)d_in[2];  // [E, H, I]
    const float* wu  = (const float*)d_in[3];  // [E, H, I]
    const float* wd  = (const float*)d_in[4];  // [E, I, H]
    float* out = (float*)d_out;                // [1024, 2048] f32

    cudaMemsetAsync(out, 0, (size_t)NTOK * HDIM * sizeof(float), 0);
    zero_counts_kernel<<<1, 32>>>();
    router_kernel<<<NTOK, 256>>>(x, gw);

    dim3 g1(IDIM / 64, NTOK / 64, NEXP);   // (22, 16, 16), most tiles early-exit
    gemm1_kernel<<<g1, 256>>>(x, wg, wu);

    dim3 g2(HDIM / 64, NTOK / 64, NEXP);   // (32, 16, 16)
    gemm2_kernel<<<g2, 256>>>(wd, out);
}

// round 14
// speedup vs baseline: 2.3765x; 2.3750x over previous
#include <cuda_runtime.h>
#include <math.h>
#include <stdint.h>

#define NTOK 1024          // B*S
#define HDIM 2048
#define NEXP 16
#define IDIM 1408

#define APITCH 36
#define BPITCH 72

// ---------------- scratch (static device globals; no allocations) ----------
__device__ int   g_cnt[NEXP];
__device__ int   g_tok[NEXP * NTOK];     // packed: token*2 + slot
__device__ float g_wt [NEXP * NTOK];     // renormalized routing weight
__device__ float g_act[2 * NTOK * IDIM]; // silu(g)*u per (token,slot)

// ---------------- helpers ---------------------------------------------------
__device__ __forceinline__ float tf32r(float x) {
    uint32_t u;
    asm("cvt.rna.tf32.f32 %0, %1;" : "=r"(u) : "f"(x));
    return __uint_as_float(u);
}

__device__ __forceinline__ void mma8(float* d, const uint32_t* a, const uint32_t* b) {
    asm volatile("mma.sync.aligned.m16n8k8.row.col.f32.tf32.tf32.f32 "
                 "{%0,%1,%2,%3}, {%4,%5,%6,%7}, {%8,%9}, {%0,%1,%2,%3};"
                 : "+f"(d[0]), "+f"(d[1]), "+f"(d[2]), "+f"(d[3])
                 : "r"(a[0]), "r"(a[1]), "r"(a[2]), "r"(a[3]),
                   "r"(b[0]), "r"(b[1]));
}

// ---------------- kernel 0: zero counters ----------------------------------
__global__ void zero_counts_kernel() {
    if (threadIdx.x < NEXP) g_cnt[threadIdx.x] = 0;
}

// ---------------- kernel 1: router (fp32, unchanged) -----------------------
__global__ void router_kernel(const float* __restrict__ x,
                              const float* __restrict__ gw) {
    const int t = blockIdx.x;
    const float* xr = x + (size_t)t * HDIM;
    __shared__ float logits[NEXP];

    const int warp = threadIdx.x >> 5;
    const int lane = threadIdx.x & 31;

    for (int e = warp; e < NEXP; e += 8) {
        const float* w = gw + (size_t)e * HDIM;
        float s = 0.f;
        for (int k = lane; k < HDIM; k += 32)
            s = fmaf(xr[k], w[k], s);
        #pragma unroll
        for (int o = 16; o; o >>= 1) s += __shfl_xor_sync(0xffffffffu, s, o);
        if (lane == 0) logits[e] = s;
    }
    __syncthreads();

    if (threadIdx.x == 0) {
        int e1 = 0; float l1 = logits[0];
        #pragma unroll
        for (int e = 1; e < NEXP; e++)
            if (logits[e] > l1) { l1 = logits[e]; e1 = e; }
        int e2 = -1; float l2 = -INFINITY;
        #pragma unroll
        for (int e = 0; e < NEXP; e++)
            if (e != e1 && logits[e] > l2) { l2 = logits[e]; e2 = e; }
        float w1 = 1.f / (1.f + expf(l2 - l1));   // p1/(p1+p2)
        float w2 = 1.f - w1;
        int p1 = atomicAdd(&g_cnt[e1], 1);
        g_tok[e1 * NTOK + p1] = t * 2 + 0;
        g_wt [e1 * NTOK + p1] = w1;
        int p2 = atomicAdd(&g_cnt[e2], 1);
        g_tok[e2 * NTOK + p2] = t * 2 + 1;
        g_wt [e2 * NTOK + p2] = w2;
    }
}

// ============================================================================
// GEMM1 (tf32 mma): act[slot][i] = silu(x@Wg) * (x@Wu)
// BM=64 BN=64 BK=32, 8 warps in 2(M)x4(N), warp tile 32x16.
// ============================================================================
__global__ __launch_bounds__(256, 2)
void gemm1_tc(const float* __restrict__ x,
              const float* __restrict__ wg,
              const float* __restrict__ wu) {
    const int e   = blockIdx.z;
    const int cnt = g_cnt[e];
    const int m0  = blockIdx.y * 64;
    if (m0 >= cnt) return;
    const int n0  = blockIdx.x * 64;

    __shared__ __align__(16) float As[64 * APITCH];  // [m][k], pitch 36
    __shared__ __align__(16) float Bg[32 * BPITCH];  // [k][n], pitch 72
    __shared__ __align__(16) float Bu[32 * BPITCH];
    __shared__ int toks[64];

    const int tid = threadIdx.x;
    if (tid < 64) {
        int r = m0 + tid;
        toks[tid] = (r < cnt) ? g_tok[e * NTOK + r] : -1;
    }
    __syncthreads();

    // ---- loader assignments
    const int am  = tid >> 2;            // A row 0..63
    const int ac  = (tid & 3) * 8;       // A col base (2x float4)
    const int apk = toks[am];
    const float* aptr = x + (size_t)((apk >= 0 ? apk : 0) >> 1) * HDIM + ac;

    const int bk = tid >> 4;             // 0..15 (+16 for second row)
    const int bn = (tid & 15) * 4;
    const size_t bstep16 = (size_t)16 * IDIM;
    const float* gptr = wg + (size_t)e * HDIM * IDIM + (size_t)bk * IDIM + n0 + bn;
    const float* uptr = wu + (size_t)e * HDIM * IDIM + (size_t)bk * IDIM + n0 + bn;

    // ---- mma thread mapping
    const int lane = tid & 31, wid = tid >> 5;
    const int mw = (wid & 1) * 32;
    const int nw = (wid >> 1) * 16;
    const int g  = lane >> 2, q = lane & 3;

    float accG[2][2][4] = {};
    float accU[2][2][4] = {};

    // prologue loads (k0 = 0)
    float4 rA0 = *(const float4*)(aptr);
    float4 rA1 = *(const float4*)(aptr + 4);
    float4 rG0 = *(const float4*)(gptr);
    float4 rG1 = *(const float4*)(gptr + bstep16);
    float4 rU0 = *(const float4*)(uptr);
    float4 rU1 = *(const float4*)(uptr + bstep16);

    for (int k0 = 0; k0 < HDIM; k0 += 32) {
        // ---- STS (tf32-converted)
        {
            float* a_s = As + am * APITCH + ac;
            *(float4*)(a_s)     = make_float4(tf32r(rA0.x), tf32r(rA0.y), tf32r(rA0.z), tf32r(rA0.w));
            *(float4*)(a_s + 4) = make_float4(tf32r(rA1.x), tf32r(rA1.y), tf32r(rA1.z), tf32r(rA1.w));
            float* bg_s = Bg + bk * BPITCH + bn;
            *(float4*)(bg_s)                = make_float4(tf32r(rG0.x), tf32r(rG0.y), tf32r(rG0.z), tf32r(rG0.w));
            *(float4*)(bg_s + 16 * BPITCH)  = make_float4(tf32r(rG1.x), tf32r(rG1.y), tf32r(rG1.z), tf32r(rG1.w));
            float* bu_s = Bu + bk * BPITCH + bn;
            *(float4*)(bu_s)                = make_float4(tf32r(rU0.x), tf32r(rU0.y), tf32r(rU0.z), tf32r(rU0.w));
            *(float4*)(bu_s + 16 * BPITCH)  = make_float4(tf32r(rU1.x), tf32r(rU1.y), tf32r(rU1.z), tf32r(rU1.w));
        }
        __syncthreads();

        // ---- prefetch next k tile into regs
        if (k0 + 32 < HDIM) {
            aptr += 32;
            gptr += 2 * bstep16;
            uptr += 2 * bstep16;
            rA0 = *(const float4*)(aptr);
            rA1 = *(const float4*)(aptr + 4);
            rG0 = *(const float4*)(gptr);
            rG1 = *(const float4*)(gptr + bstep16);
            rU0 = *(const float4*)(uptr);
            rU1 = *(const float4*)(uptr + bstep16);
        }

        // ---- compute: 4 k8 steps
        #pragma unroll
        for (int kk = 0; kk < 32; kk += 8) {
            uint32_t a[2][4];
            #pragma unroll
            for (int mi = 0; mi < 2; mi++) {
                const float* ab = As + (mw + mi * 16 + g) * APITCH + kk + q;
                a[mi][0] = __float_as_uint(ab[0]);
                a[mi][1] = __float_as_uint(ab[8 * APITCH]);
                a[mi][2] = __float_as_uint(ab[4]);
                a[mi][3] = __float_as_uint(ab[8 * APITCH + 4]);
            }
            #pragma unroll
            for (int ni = 0; ni < 2; ni++) {
                const float* gb = Bg + (kk + q) * BPITCH + nw + ni * 8 + g;
                const float* ub = Bu + (kk + q) * BPITCH + nw + ni * 8 + g;
                uint32_t bgf[2] = { __float_as_uint(gb[0]), __float_as_uint(gb[4 * BPITCH]) };
                uint32_t buf[2] = { __float_as_uint(ub[0]), __float_as_uint(ub[4 * BPITCH]) };
                #pragma unroll
                for (int mi = 0; mi < 2; mi++) {
                    mma8(accG[mi][ni], a[mi], bgf);
                    mma8(accU[mi][ni], a[mi], buf);
                }
            }
        }
        __syncthreads();
    }

    // ---- epilogue: silu(g)*u -> g_act
    #pragma unroll
    for (int mi = 0; mi < 2; mi++) {
        #pragma unroll
        for (int half = 0; half < 2; half++) {
            int row = mw + mi * 16 + g + half * 8;
            int pk  = toks[row];
            if (pk < 0) continue;
            float* dst = g_act + (size_t)pk * IDIM + n0 + nw + 2 * q;
            #pragma unroll
            for (int ni = 0; ni < 2; ni++) {
                float gg = accG[mi][ni][half * 2 + 0];
                float uu = accU[mi][ni][half * 2 + 0];
                float o0 = (gg / (1.f + expf(-gg))) * uu;
                gg = accG[mi][ni][half * 2 + 1];
                uu = accU[mi][ni][half * 2 + 1];
                float o1 = (gg / (1.f + expf(-gg))) * uu;
                *(float2*)(dst + ni * 8) = make_float2(o0, o1);
            }
        }
    }
}

// ============================================================================
// GEMM2 (tf32 mma): out[tok] += w * (act[slot] @ w_down[e])
// ============================================================================
__global__ __launch_bounds__(256, 2)
void gemm2_tc(const float* __restrict__ wd,
              float* __restrict__ out) {
    const int e   = blockIdx.z;
    const int cnt = g_cnt[e];
    const int m0  = blockIdx.y * 64;
    if (m0 >= cnt) return;
    const int n0  = blockIdx.x * 64;

    __shared__ __align__(16) float As[64 * APITCH];
    __shared__ __align__(16) float Bs[32 * BPITCH];
    __shared__ int   toks[64];
    __shared__ float wts[64];

    const int tid = threadIdx.x;
    if (tid < 64) {
        int r = m0 + tid;
        if (r < cnt) {
            toks[tid] = g_tok[e * NTOK + r];
            wts[tid]  = g_wt [e * NTOK + r];
        } else {
            toks[tid] = -1;
            wts[tid]  = 0.f;
        }
    }
    __syncthreads();

    const int am  = tid >> 2;
    const int ac  = (tid & 3) * 8;
    const int apk = toks[am];
    const float* aptr = g_act + (size_t)(apk >= 0 ? apk : 0) * IDIM + ac;

    const int bk = tid >> 4;
    const int bn = (tid & 15) * 4;
    const size_t bstep16 = (size_t)16 * HDIM;
    const float* bptr = wd + (size_t)e * IDIM * HDIM + (size_t)bk * HDIM + n0 + bn;

    const int lane = tid & 31, wid = tid >> 5;
    const int mw = (wid & 1) * 32;
    const int nw = (wid >> 1) * 16;
    const int g  = lane >> 2, q = lane & 3;

    float acc[2][2][4] = {};

    float4 rA0 = *(const float4*)(aptr);
    float4 rA1 = *(const float4*)(aptr + 4);
    float4 rB0 = *(const float4*)(bptr);
    float4 rB1 = *(const float4*)(bptr + bstep16);

    for (int k0 = 0; k0 < IDIM; k0 += 32) {
        {
            float* a_s = As + am * APITCH + ac;
            *(float4*)(a_s)     = make_float4(tf32r(rA0.x), tf32r(rA0.y), tf32r(rA0.z), tf32r(rA0.w));
            *(float4*)(a_s + 4) = make_float4(tf32r(rA1.x), tf32r(rA1.y), tf32r(rA1.z), tf32r(rA1.w));
            float* b_s = Bs + bk * BPITCH + bn;
            *(float4*)(b_s)               = make_float4(tf32r(rB0.x), tf32r(rB0.y), tf32r(rB0.z), tf32r(rB0.w));
            *(float4*)(b_s + 16 * BPITCH) = make_float4(tf32r(rB1.x), tf32r(rB1.y), tf32r(rB1.z), tf32r(rB1.w));
        }
        __syncthreads();

        if (k0 + 32 < IDIM) {
            aptr += 32;
            bptr += 2 * bstep16;
            rA0 = *(const float4*)(aptr);
            rA1 = *(const float4*)(aptr + 4);
            rB0 = *(const float4*)(bptr);
            rB1 = *(const float4*)(bptr + bstep16);
        }

        #pragma unroll
        for (int kk = 0; kk < 32; kk += 8) {
            uint32_t a[2][4];
            #pragma unroll
            for (int mi = 0; mi < 2; mi++) {
                const float* ab = As + (mw + mi * 16 + g) * APITCH + kk + q;
                a[mi][0] = __float_as_uint(ab[0]);
                a[mi][1] = __float_as_uint(ab[8 * APITCH]);
                a[mi][2] = __float_as_uint(ab[4]);
                a[mi][3] = __float_as_uint(ab[8 * APITCH + 4]);
            }
            #pragma unroll
            for (int ni = 0; ni < 2; ni++) {
                const float* bb = Bs + (kk + q) * BPITCH + nw + ni * 8 + g;
                uint32_t bf[2] = { __float_as_uint(bb[0]), __float_as_uint(bb[4 * BPITCH]) };
                #pragma unroll
                for (int mi = 0; mi < 2; mi++)
                    mma8(acc[mi][ni], a[mi], bf);
            }
        }
        __syncthreads();
    }

    // ---- epilogue: weighted atomic scatter into out
    #pragma unroll
    for (int mi = 0; mi < 2; mi++) {
        #pragma unroll
        for (int half = 0; half < 2; half++) {
            int row = mw + mi * 16 + g + half * 8;
            int pk  = toks[row];
            if (pk < 0) continue;
            float w   = wts[row];
            int   tok = pk >> 1;
            float* dst = out + (size_t)tok * HDIM + n0 + nw + 2 * q;
            #pragma unroll
            for (int ni = 0; ni < 2; ni++) {
                atomicAdd(dst + ni * 8 + 0, w * acc[mi][ni][half * 2 + 0]);
                atomicAdd(dst + ni * 8 + 1, w * acc[mi][ni][half * 2 + 1]);
            }
        }
    }
}

// ---------------- launch ----------------------------------------------------
extern "C" void kernel_launch(void* const* d_in, const int* in_sizes, int n_in,
                              void* d_out, int out_size) {
    const float* x   = (const float*)d_in[0];  // [1024, 2048]
    const float* gw  = (const float*)d_in[1];  // [E, H]
    const float* wg  = (const float*)d_in[2];  // [E, H, I]
    const float* wu  = (const float*)d_in[3];  // [E, H, I]
    const float* wd  = (const float*)d_in[4];  // [E, I, H]
    float* out = (float*)d_out;                // [1024, 2048] f32

    cudaMemsetAsync(out, 0, (size_t)NTOK * HDIM * sizeof(float), 0);
    zero_counts_kernel<<<1, 32>>>();
    router_kernel<<<NTOK, 256>>>(x, gw);

    dim3 g1(IDIM / 64, NTOK / 64, NEXP);   // (22, 16, 16); dead tiles early-exit
    gemm1_tc<<<g1, 256>>>(x, wg, wu);

    dim3 g2(HDIM / 64, NTOK / 64, NEXP);   // (32, 16, 16)
    gemm2_tc<<<g2, 256>>>(wd, out);
}